// round 10
// baseline (speedup 1.0000x reference)
#include <cuda_runtime.h>
#include <cuda_bf16.h>

#define NN 100000
#define EE 1600000
#define FIN 128
#define HID 64
#define NOUT 40
#define SCAN_B 512
#define NBS ((NN + SCAN_B - 1) / SCAN_B)   // 196 blocks

// Scratch (allocation-free rule: __device__ globals)
__device__ float g_dis[NN];
__device__ int   g_cnt[NN];        // edge in-degree (excl self loop)
__device__ int   g_rowstart[NN];   // CSR row start
__device__ int   g_fill[NN];       // scatter fill counters
__device__ int   g_blocksum[256];  // scan partials
__device__ int   g_ssrc[EE];       // dst-sorted src indices
__device__ float g_h[(size_t)NN * HID];    // hs = dis * (XW+b)
__device__ float g_agg[(size_t)NN * HID];  // aggregated features

// ---------------- degree histogram ----------------
__global__ void k_zero() {
    int i = blockIdx.x * blockDim.x + threadIdx.x;
    if (i < NN) { g_cnt[i] = 0; g_fill[i] = 0; }
}

__global__ void k_count(const int* __restrict__ dst) {
    int e = blockIdx.x * blockDim.x + threadIdx.x;
    if (e < EE) atomicAdd(&g_cnt[dst[e]], 1);
}

__global__ void k_dis() {
    int i = blockIdx.x * blockDim.x + threadIdx.x;
    if (i < NN) g_dis[i] = rsqrtf((float)(g_cnt[i] + 1));  // +1 self loop
}

// ---------------- 2-level exclusive scan of g_cnt -> g_rowstart ----------------
__global__ __launch_bounds__(SCAN_B) void k_scan1() {
    __shared__ int sh[SCAN_B];
    int t = threadIdx.x;
    int i = blockIdx.x * SCAN_B + t;
    int v = (i < NN) ? g_cnt[i] : 0;
    sh[t] = v;
    __syncthreads();
#pragma unroll
    for (int o = 1; o < SCAN_B; o <<= 1) {
        int add = (t >= o) ? sh[t - o] : 0;
        __syncthreads();
        sh[t] += add;
        __syncthreads();
    }
    if (i < NN) g_rowstart[i] = sh[t] - v;          // exclusive
    if (t == SCAN_B - 1) g_blocksum[blockIdx.x] = sh[t];
}

__global__ __launch_bounds__(256) void k_scan2() {
    __shared__ int sh[256];
    int t = threadIdx.x;
    int v = (t < NBS) ? g_blocksum[t] : 0;
    sh[t] = v;
    __syncthreads();
#pragma unroll
    for (int o = 1; o < 256; o <<= 1) {
        int add = (t >= o) ? sh[t - o] : 0;
        __syncthreads();
        sh[t] += add;
        __syncthreads();
    }
    if (t < NBS) g_blocksum[t] = sh[t] - v;         // exclusive
}

__global__ __launch_bounds__(SCAN_B) void k_scan3() {
    int i = blockIdx.x * SCAN_B + threadIdx.x;
    if (i < NN) g_rowstart[i] += g_blocksum[blockIdx.x];
}

// ---------------- scatter edges into dst buckets ----------------
__global__ void k_scatter(const int* __restrict__ src, const int* __restrict__ dst) {
    int e = blockIdx.x * blockDim.x + threadIdx.x;
    if (e >= EE) return;
    int d = dst[e];
    int pos = g_rowstart[d] + atomicAdd(&g_fill[d], 1);
    g_ssrc[pos] = src[e];
}

// ---------------- GEMM: g_h[r] = dis[r] * (act(in[r]) @ W + b) ----------------
// IN: 0 = external ptr, 1 = g_agg.
template<int K, int ROWS, bool RELU, int IN>
__global__ __launch_bounds__(256) void k_gemm(
    const float* __restrict__ in_ext, const float* __restrict__ W,
    const float* __restrict__ bias, int nrows)
{
    __shared__ float Xs[ROWS * K];
    __shared__ float Ws[K * 64];
    const float* in = (IN == 0) ? in_ext : g_agg;
    const int tid  = threadIdx.x;
    const int row0 = blockIdx.x * ROWS;

    for (int i = tid; i < K * 64 / 4; i += 256)
        ((float4*)Ws)[i] = ((const float4*)W)[i];
    for (int i = tid; i < ROWS * K / 4; i += 256) {
        int r  = i / (K / 4);
        float4 v = make_float4(0.f, 0.f, 0.f, 0.f);
        if (row0 + r < nrows) {
            int c4 = i % (K / 4);
            v = ((const float4*)(in + (size_t)(row0 + r) * K))[c4];
        }
        if (RELU) {
            v.x = fmaxf(v.x, 0.f); v.y = fmaxf(v.y, 0.f);
            v.z = fmaxf(v.z, 0.f); v.w = fmaxf(v.w, 0.f);
        }
        ((float4*)Xs)[i] = v;
    }
    __syncthreads();

    const int cg = tid & 15;        // 16 col groups x 4 cols
    const int rg = tid >> 4;        // 16 row groups
    constexpr int RPT = ROWS / 16;
    const int c = cg * 4;
    const int r = rg * RPT;

    float acc[RPT][4];
#pragma unroll
    for (int j = 0; j < RPT; ++j) { acc[j][0]=0.f; acc[j][1]=0.f; acc[j][2]=0.f; acc[j][3]=0.f; }

#pragma unroll 4
    for (int kk = 0; kk < K; kk += 4) {
        float4 w0 = *(const float4*)&Ws[(kk + 0) * 64 + c];
        float4 w1 = *(const float4*)&Ws[(kk + 1) * 64 + c];
        float4 w2 = *(const float4*)&Ws[(kk + 2) * 64 + c];
        float4 w3 = *(const float4*)&Ws[(kk + 3) * 64 + c];
#pragma unroll
        for (int j = 0; j < RPT; ++j) {
            float4 xv = *(const float4*)&Xs[(r + j) * K + kk];
            acc[j][0] += xv.x * w0.x + xv.y * w1.x + xv.z * w2.x + xv.w * w3.x;
            acc[j][1] += xv.x * w0.y + xv.y * w1.y + xv.z * w2.y + xv.w * w3.y;
            acc[j][2] += xv.x * w0.z + xv.y * w1.z + xv.z * w2.z + xv.w * w3.z;
            acc[j][3] += xv.x * w0.w + xv.y * w1.w + xv.z * w2.w + xv.w * w3.w;
        }
    }

    float4 bb = *(const float4*)&bias[c];
#pragma unroll
    for (int j = 0; j < RPT; ++j) {
        int row = row0 + r + j;
        if (row < nrows) {
            float s = g_dis[row];
            float4 o;
            o.x = (acc[j][0] + bb.x) * s; o.y = (acc[j][1] + bb.y) * s;
            o.z = (acc[j][2] + bb.z) * s; o.w = (acc[j][3] + bb.w) * s;
            *(float4*)(g_h + (size_t)row * 64 + c) = o;
        }
    }
}

// ---------------- CSR gather: agg[d] = dis[d] * (hs[d] + sum_src hs[src]) ----------------
// 8 threads per node, each owns 8 floats (2 x float4) of the feature vector.
__global__ __launch_bounds__(256) void k_gather() {
    int t = blockIdx.x * blockDim.x + threadIdx.x;
    int node = t >> 3;
    int c = t & 7;             // chunk pair index: float4s [2c, 2c+1]
    if (node >= NN) return;
    const float4* hs = (const float4*)g_h;
    size_t base = (size_t)node * 16 + c * 2;
    float4 a0 = hs[base];
    float4 a1 = hs[base + 1];   // self term
    int beg = g_rowstart[node];
    int end = beg + g_cnt[node];
    int e = beg;
    // 4 neighbors per iter -> 8 outstanding LDG.128 per thread
    for (; e + 4 <= end; e += 4) {
        int s0 = __ldg(&g_ssrc[e + 0]);
        int s1 = __ldg(&g_ssrc[e + 1]);
        int s2 = __ldg(&g_ssrc[e + 2]);
        int s3 = __ldg(&g_ssrc[e + 3]);
        size_t b0 = (size_t)s0 * 16 + c * 2;
        size_t b1 = (size_t)s1 * 16 + c * 2;
        size_t b2 = (size_t)s2 * 16 + c * 2;
        size_t b3 = (size_t)s3 * 16 + c * 2;
        float4 u0 = __ldg(hs + b0), w0 = __ldg(hs + b0 + 1);
        float4 u1 = __ldg(hs + b1), w1 = __ldg(hs + b1 + 1);
        float4 u2 = __ldg(hs + b2), w2 = __ldg(hs + b2 + 1);
        float4 u3 = __ldg(hs + b3), w3 = __ldg(hs + b3 + 1);
        a0.x += (u0.x + u1.x) + (u2.x + u3.x);
        a0.y += (u0.y + u1.y) + (u2.y + u3.y);
        a0.z += (u0.z + u1.z) + (u2.z + u3.z);
        a0.w += (u0.w + u1.w) + (u2.w + u3.w);
        a1.x += (w0.x + w1.x) + (w2.x + w3.x);
        a1.y += (w0.y + w1.y) + (w2.y + w3.y);
        a1.z += (w0.z + w1.z) + (w2.z + w3.z);
        a1.w += (w0.w + w1.w) + (w2.w + w3.w);
    }
    for (; e < end; ++e) {
        int s = __ldg(&g_ssrc[e]);
        size_t b = (size_t)s * 16 + c * 2;
        float4 u = __ldg(hs + b), w = __ldg(hs + b + 1);
        a0.x += u.x; a0.y += u.y; a0.z += u.z; a0.w += u.w;
        a1.x += w.x; a1.y += w.y; a1.z += w.z; a1.w += w.w;
    }
    float d = g_dis[node];
    a0.x *= d; a0.y *= d; a0.z *= d; a0.w *= d;
    a1.x *= d; a1.y *= d; a1.z *= d; a1.w *= d;
    ((float4*)g_agg)[base]     = a0;
    ((float4*)g_agg)[base + 1] = a1;
}

// ---------------- output layer: out[r] = relu(agg[r]) @ Wout + bout ----------------
__global__ __launch_bounds__(256) void k_final(
    const float* __restrict__ W, const float* __restrict__ bias,
    float* __restrict__ out, int nrows)
{
    __shared__ float Xs[64 * 64];
    __shared__ float Ws[64 * NOUT];
    __shared__ float bs[NOUT];
    const int tid  = threadIdx.x;
    const int row0 = blockIdx.x * 64;

    for (int i = tid; i < 64 * NOUT / 4; i += 256)
        ((float4*)Ws)[i] = ((const float4*)W)[i];
    if (tid < NOUT) bs[tid] = bias[tid];
    for (int i = tid; i < 64 * 64 / 4; i += 256) {
        int r = i >> 4;
        float4 v = make_float4(0.f, 0.f, 0.f, 0.f);
        if (row0 + r < nrows) {
            int c4 = i & 15;
            v = ((const float4*)(g_agg + (size_t)(row0 + r) * 64))[c4];
        }
        v.x = fmaxf(v.x, 0.f); v.y = fmaxf(v.y, 0.f);
        v.z = fmaxf(v.z, 0.f); v.w = fmaxf(v.w, 0.f);
        ((float4*)Xs)[i] = v;
    }
    __syncthreads();

    for (int o = tid; o < 64 * NOUT; o += 256) {
        int r = o / NOUT, c = o % NOUT;
        float acc = 0.f;
#pragma unroll 8
        for (int k = 0; k < 64; ++k)
            acc += Xs[r * 64 + k] * Ws[k * NOUT + c];
        if (row0 + r < nrows)
            out[(size_t)(row0 + r) * NOUT + c] = acc + bs[c];
    }
}

// ---------------- launch: pure kernel launches only ----------------
extern "C" void kernel_launch(void* const* d_in, const int* in_sizes, int n_in,
                              void* d_out, int out_size)
{
    const float* x    = (const float*)d_in[0];
    const int*   ei   = (const int*)d_in[1];
    const int*   src  = ei;
    const int*   dst  = ei + EE;
    const float* W0   = (const float*)d_in[2];
    const float* b0   = (const float*)d_in[3];
    const float* W1   = (const float*)d_in[4];
    const float* b1   = (const float*)d_in[5];
    const float* W2   = (const float*)d_in[6];
    const float* b2   = (const float*)d_in[7];
    const float* Wout = (const float*)d_in[8];
    const float* bout = (const float*)d_in[9];
    float* out = (float*)d_out;

    const int nb_n      = (NN + 255) / 256;
    const int nb_e      = (EE + 255) / 256;
    const int nb_gather = (NN * 8 + 255) / 256;
    const int nb_g128   = (NN + 31) / 32;
    const int nb_g64    = (NN + 63) / 64;

    // ---- degree + norm (gemm1 placed 4th so ncu -s 5 profiles it) ----
    k_zero<<<nb_n, 256>>>();
    k_count<<<nb_e, 256>>>(dst);
    k_dis<<<nb_n, 256>>>();

    // ---- layer 1 transform (needs only g_dis) ----
    k_gemm<128, 32, false, 0><<<nb_g128, 256>>>(x, W0, b0, NN);

    // ---- CSR build ----
    k_scan1<<<NBS, SCAN_B>>>();
    k_scan2<<<1, 256>>>();
    k_scan3<<<NBS, SCAN_B>>>();
    k_scatter<<<nb_e, 256>>>(src, dst);

    // ---- layer 1 aggregate ----
    k_gather<<<nb_gather, 256>>>();

    // ---- layer 2 ----
    k_gemm<64, 64, true, 1><<<nb_g64, 256>>>(nullptr, W1, b1, NN);
    k_gather<<<nb_gather, 256>>>();

    // ---- layer 3 ----
    k_gemm<64, 64, true, 1><<<nb_g64, 256>>>(nullptr, W2, b2, NN);
    k_gather<<<nb_gather, 256>>>();

    // ---- output ----
    k_final<<<nb_g64, 256>>>(Wout, bout, out, NN);
}

// round 12
// speedup vs baseline: 1.1686x; 1.1686x over previous
#include <cuda_runtime.h>
#include <cuda_bf16.h>

#define NN 100000
#define EE 1600000
#define FIN 128
#define HID 64
#define NOUT 40
#define SCAN_B 512
#define NBS ((NN + SCAN_B - 1) / SCAN_B)   // 196 blocks

// Scratch (allocation-free rule: __device__ globals)
__device__ float g_dis[NN];
__device__ int   g_cnt[NN];        // edge in-degree (excl self loop)
__device__ int   g_rowstart[NN];   // CSR row start
__device__ int   g_fill[NN];       // scatter fill counters
__device__ int   g_blocksum[256];  // scan partials
__device__ int   g_ssrc[EE];       // dst-sorted src indices
__device__ float g_h[(size_t)NN * HID];    // hs = dis * (XW+b)
__device__ float g_agg[(size_t)NN * HID];  // aggregated features

// ---------------- degree histogram ----------------
__global__ void k_zero() {
    int i = blockIdx.x * blockDim.x + threadIdx.x;
    if (i < NN) { g_cnt[i] = 0; g_fill[i] = 0; }
}

__global__ void k_count(const int* __restrict__ dst) {
    int e = blockIdx.x * blockDim.x + threadIdx.x;
    if (e < EE) atomicAdd(&g_cnt[dst[e]], 1);
}

__global__ void k_dis() {
    int i = blockIdx.x * blockDim.x + threadIdx.x;
    if (i < NN) g_dis[i] = rsqrtf((float)(g_cnt[i] + 1));  // +1 self loop
}

// ---------------- 2-level exclusive scan of g_cnt -> g_rowstart ----------------
__global__ __launch_bounds__(SCAN_B) void k_scan1() {
    __shared__ int sh[SCAN_B];
    int t = threadIdx.x;
    int i = blockIdx.x * SCAN_B + t;
    int v = (i < NN) ? g_cnt[i] : 0;
    sh[t] = v;
    __syncthreads();
#pragma unroll
    for (int o = 1; o < SCAN_B; o <<= 1) {
        int add = (t >= o) ? sh[t - o] : 0;
        __syncthreads();
        sh[t] += add;
        __syncthreads();
    }
    if (i < NN) g_rowstart[i] = sh[t] - v;          // exclusive
    if (t == SCAN_B - 1) g_blocksum[blockIdx.x] = sh[t];
}

__global__ __launch_bounds__(256) void k_scan2() {
    __shared__ int sh[256];
    int t = threadIdx.x;
    int v = (t < NBS) ? g_blocksum[t] : 0;
    sh[t] = v;
    __syncthreads();
#pragma unroll
    for (int o = 1; o < 256; o <<= 1) {
        int add = (t >= o) ? sh[t - o] : 0;
        __syncthreads();
        sh[t] += add;
        __syncthreads();
    }
    if (t < NBS) g_blocksum[t] = sh[t] - v;         // exclusive
}

__global__ __launch_bounds__(SCAN_B) void k_scan3() {
    int i = blockIdx.x * SCAN_B + threadIdx.x;
    if (i < NN) g_rowstart[i] += g_blocksum[blockIdx.x];
}

// ---------------- scatter edges into dst buckets ----------------
__global__ void k_scatter(const int* __restrict__ src, const int* __restrict__ dst) {
    int e = blockIdx.x * blockDim.x + threadIdx.x;
    if (e >= EE) return;
    int d = dst[e];
    int pos = g_rowstart[d] + atomicAdd(&g_fill[d], 1);
    g_ssrc[pos] = src[e];
}

// ---------------- GEMM: g_h[r] = dis[r] * (act(in[r]) @ W + b) ----------------
// 128-row tile, 8 rows x 4 cols per thread (1.5 B LDS per FMA).
// K processed in KH=64 halves so smem = 32KB Xs + 16KB Ws = 48KB.
// IN: 0 = external ptr, 1 = g_agg.
template<int K, bool RELU, int IN>
__global__ __launch_bounds__(256, 2) void k_gemm(
    const float* __restrict__ in_ext, const float* __restrict__ W,
    const float* __restrict__ bias, int nrows)
{
    constexpr int KH = 64;
    constexpr int NH = K / KH;
    __shared__ float Xs[128 * KH];   // 32KB
    __shared__ float Ws[KH * 64];    // 16KB
    const float* in = (IN == 0) ? in_ext : g_agg;
    const int tid  = threadIdx.x;
    const int row0 = blockIdx.x * 128;
    const int cg = tid & 15;        // 16 col groups x 4 cols
    const int rg = tid >> 4;        // 16 row groups x 8 rows
    const int c = cg * 4;
    const int r = rg * 8;

    float acc[8][4];
#pragma unroll
    for (int j = 0; j < 8; ++j) { acc[j][0]=0.f; acc[j][1]=0.f; acc[j][2]=0.f; acc[j][3]=0.f; }

    for (int h = 0; h < NH; ++h) {
        if (h > 0) __syncthreads();   // protect smem reuse across halves
        // stage W half: W[(h*KH + k)*64 + col]
        for (int i = tid; i < KH * 64 / 4; i += 256)
            ((float4*)Ws)[i] = ((const float4*)(W + h * KH * 64))[i];
        // stage X rows for this k-half, optional input ReLU
        for (int i = tid; i < 128 * KH / 4; i += 256) {
            int rr = i / (KH / 4);
            float4 v = make_float4(0.f, 0.f, 0.f, 0.f);
            int grow = row0 + rr;
            if (grow < nrows) {
                int c4 = i % (KH / 4);
                v = ((const float4*)(in + (size_t)grow * K + h * KH))[c4];
            }
            if (RELU) {
                v.x = fmaxf(v.x, 0.f); v.y = fmaxf(v.y, 0.f);
                v.z = fmaxf(v.z, 0.f); v.w = fmaxf(v.w, 0.f);
            }
            ((float4*)Xs)[i] = v;
        }
        __syncthreads();

        for (int kk = 0; kk < KH; kk += 4) {
            float4 w0 = *(const float4*)&Ws[(kk + 0) * 64 + c];
            float4 w1 = *(const float4*)&Ws[(kk + 1) * 64 + c];
            float4 w2 = *(const float4*)&Ws[(kk + 2) * 64 + c];
            float4 w3 = *(const float4*)&Ws[(kk + 3) * 64 + c];
#pragma unroll
            for (int j = 0; j < 8; ++j) {
                float4 xv = *(const float4*)&Xs[(r + j) * KH + kk];
                acc[j][0] += xv.x * w0.x + xv.y * w1.x + xv.z * w2.x + xv.w * w3.x;
                acc[j][1] += xv.x * w0.y + xv.y * w1.y + xv.z * w2.y + xv.w * w3.y;
                acc[j][2] += xv.x * w0.z + xv.y * w1.z + xv.z * w2.z + xv.w * w3.z;
                acc[j][3] += xv.x * w0.w + xv.y * w1.w + xv.z * w2.w + xv.w * w3.w;
            }
        }
    }

    float4 bb = *(const float4*)&bias[c];
#pragma unroll
    for (int j = 0; j < 8; ++j) {
        int row = row0 + r + j;
        if (row < nrows) {
            float s = g_dis[row];
            float4 o;
            o.x = (acc[j][0] + bb.x) * s; o.y = (acc[j][1] + bb.y) * s;
            o.z = (acc[j][2] + bb.z) * s; o.w = (acc[j][3] + bb.w) * s;
            *(float4*)(g_h + (size_t)row * 64 + c) = o;
        }
    }
}

// ---------------- CSR gather: agg[d] = dis[d] * (hs[d] + sum_src hs[src]) ----------------
// 8 threads per node; thread c owns float4 lanes c and c+8 (both LDGs 128B-contiguous
// across the 8 threads -> fully-used sectors, 1 line per LDG per node).
__global__ __launch_bounds__(256) void k_gather() {
    int t = blockIdx.x * blockDim.x + threadIdx.x;
    int node = t >> 3;
    int c = t & 7;
    if (node >= NN) return;
    const float4* hs = (const float4*)g_h;
    size_t base = (size_t)node * 16;
    float4 a0 = hs[base + c];
    float4 a1 = hs[base + 8 + c];   // self term
    int beg = g_rowstart[node];
    int end = beg + g_cnt[node];
    int e = beg;
    // 4 neighbors per iter -> 8 outstanding LDG.128 per thread
    for (; e + 4 <= end; e += 4) {
        int s0 = __ldg(&g_ssrc[e + 0]);
        int s1 = __ldg(&g_ssrc[e + 1]);
        int s2 = __ldg(&g_ssrc[e + 2]);
        int s3 = __ldg(&g_ssrc[e + 3]);
        size_t b0 = (size_t)s0 * 16;
        size_t b1 = (size_t)s1 * 16;
        size_t b2 = (size_t)s2 * 16;
        size_t b3 = (size_t)s3 * 16;
        float4 u0 = __ldg(hs + b0 + c), w0 = __ldg(hs + b0 + 8 + c);
        float4 u1 = __ldg(hs + b1 + c), w1 = __ldg(hs + b1 + 8 + c);
        float4 u2 = __ldg(hs + b2 + c), w2 = __ldg(hs + b2 + 8 + c);
        float4 u3 = __ldg(hs + b3 + c), w3 = __ldg(hs + b3 + 8 + c);
        a0.x += (u0.x + u1.x) + (u2.x + u3.x);
        a0.y += (u0.y + u1.y) + (u2.y + u3.y);
        a0.z += (u0.z + u1.z) + (u2.z + u3.z);
        a0.w += (u0.w + u1.w) + (u2.w + u3.w);
        a1.x += (w0.x + w1.x) + (w2.x + w3.x);
        a1.y += (w0.y + w1.y) + (w2.y + w3.y);
        a1.z += (w0.z + w1.z) + (w2.z + w3.z);
        a1.w += (w0.w + w1.w) + (w2.w + w3.w);
    }
    for (; e < end; ++e) {
        int s = __ldg(&g_ssrc[e]);
        size_t b = (size_t)s * 16;
        float4 u = __ldg(hs + b + c), w = __ldg(hs + b + 8 + c);
        a0.x += u.x; a0.y += u.y; a0.z += u.z; a0.w += u.w;
        a1.x += w.x; a1.y += w.y; a1.z += w.z; a1.w += w.w;
    }
    float d = g_dis[node];
    a0.x *= d; a0.y *= d; a0.z *= d; a0.w *= d;
    a1.x *= d; a1.y *= d; a1.z *= d; a1.w *= d;
    ((float4*)g_agg)[base + c]     = a0;
    ((float4*)g_agg)[base + 8 + c] = a1;
}

// ---------------- output layer: out[r] = relu(agg[r]) @ Wout + bout ----------------
__global__ __launch_bounds__(256) void k_final(
    const float* __restrict__ W, const float* __restrict__ bias,
    float* __restrict__ out, int nrows)
{
    __shared__ float Xs[64 * 64];
    __shared__ float Ws[64 * NOUT];
    __shared__ float bs[NOUT];
    const int tid  = threadIdx.x;
    const int row0 = blockIdx.x * 64;

    for (int i = tid; i < 64 * NOUT / 4; i += 256)
        ((float4*)Ws)[i] = ((const float4*)W)[i];
    if (tid < NOUT) bs[tid] = bias[tid];
    for (int i = tid; i < 64 * 64 / 4; i += 256) {
        int r = i >> 4;
        float4 v = make_float4(0.f, 0.f, 0.f, 0.f);
        if (row0 + r < nrows) {
            int c4 = i & 15;
            v = ((const float4*)(g_agg + (size_t)(row0 + r) * 64))[c4];
        }
        v.x = fmaxf(v.x, 0.f); v.y = fmaxf(v.y, 0.f);
        v.z = fmaxf(v.z, 0.f); v.w = fmaxf(v.w, 0.f);
        ((float4*)Xs)[i] = v;
    }
    __syncthreads();

    for (int o = tid; o < 64 * NOUT; o += 256) {
        int r = o / NOUT, c = o % NOUT;
        float acc = 0.f;
#pragma unroll 8
        for (int k = 0; k < 64; ++k)
            acc += Xs[r * 64 + k] * Ws[k * NOUT + c];
        if (row0 + r < nrows)
            out[(size_t)(row0 + r) * NOUT + c] = acc + bs[c];
    }
}

// ---------------- launch: pure kernel launches only ----------------
extern "C" void kernel_launch(void* const* d_in, const int* in_sizes, int n_in,
                              void* d_out, int out_size)
{
    const float* x    = (const float*)d_in[0];
    const int*   ei   = (const int*)d_in[1];
    const int*   src  = ei;
    const int*   dst  = ei + EE;
    const float* W0   = (const float*)d_in[2];
    const float* b0   = (const float*)d_in[3];
    const float* W1   = (const float*)d_in[4];
    const float* b1   = (const float*)d_in[5];
    const float* W2   = (const float*)d_in[6];
    const float* b2   = (const float*)d_in[7];
    const float* Wout = (const float*)d_in[8];
    const float* bout = (const float*)d_in[9];
    float* out = (float*)d_out;

    const int nb_n      = (NN + 255) / 256;
    const int nb_e      = (EE + 255) / 256;
    const int nb_gather = (NN * 8 + 255) / 256;
    const int nb_g      = (NN + 127) / 128;
    const int nb_f      = (NN + 63) / 64;

    // ---- degree + norm (gemm1 placed 4th so ncu -s 5 profiles it) ----
    k_zero<<<nb_n, 256>>>();
    k_count<<<nb_e, 256>>>(dst);
    k_dis<<<nb_n, 256>>>();

    // ---- layer 1 transform (needs only g_dis) ----
    k_gemm<128, false, 0><<<nb_g, 256>>>(x, W0, b0, NN);

    // ---- CSR build ----
    k_scan1<<<NBS, SCAN_B>>>();
    k_scan2<<<1, 256>>>();
    k_scan3<<<NBS, SCAN_B>>>();
    k_scatter<<<nb_e, 256>>>(src, dst);

    // ---- layer 1 aggregate ----
    k_gather<<<nb_gather, 256>>>();

    // ---- layer 2 ----
    k_gemm<64, true, 1><<<nb_g, 256>>>(nullptr, W1, b1, NN);
    k_gather<<<nb_gather, 256>>>();

    // ---- layer 3 ----
    k_gemm<64, true, 1><<<nb_g, 256>>>(nullptr, W2, b2, NN);
    k_gather<<<nb_gather, 256>>>();

    // ---- output ----
    k_final<<<nb_f, 256>>>(Wout, bout, out, NN);
}